// round 1
// baseline (speedup 1.0000x reference)
#include <cuda_runtime.h>
#include <cuda_bf16.h>
#include <math.h>

#define B_TOT   32768
#define OBS_DIM 256
#define HID     64
#define FEAT    128
#define N_OPT   8
#define ACT_N   18
#define TB      64        // rows per block (trunk & expert)

// ---------------- scratch (no allocation allowed) ----------------
__device__ float g_state[B_TOT * FEAT];   // 16 MB, L2-resident
__device__ int   g_perm[B_TOT];
__device__ int   g_counts[N_OPT];         // zero-initialized; scan kernel re-zeros each run
__device__ int   g_cursor[N_OPT];

__device__ __forceinline__ float wred_sum(float v) {
#pragma unroll
    for (int o = 16; o; o >>= 1) v += __shfl_xor_sync(0xffffffffu, v, o);
    return v;
}
__device__ __forceinline__ float wred_max(float v) {
#pragma unroll
    for (int o = 16; o; o >>= 1) v = fmaxf(v, __shfl_xor_sync(0xffffffffu, v, o));
    return v;
}

// =====================================================================
// Kernel 1: trunk GEMMs + heads + option histogram
//   h     = relu(obs @ fW1^T + fb1)        [64]
//   state = relu(h   @ fW2^T + fb2)        [128]  -> g_state
//   optval, termprob heads; histogram of opt
// =====================================================================
__global__ void __launch_bounds__(256, 2) trunk_kernel(
    const float* __restrict__ obs, const int* __restrict__ opt,
    const float* __restrict__ fW1, const float* __restrict__ fb1,
    const float* __restrict__ fW2, const float* __restrict__ fb2,
    const float* __restrict__ pW,  const float* __restrict__ pb,
    const float* __restrict__ tW,  const float* __restrict__ tb,
    float* __restrict__ out_opt, float* __restrict__ out_term)
{
    extern __shared__ float sm[];
    float* buf1 = sm;          // 8320 floats: fW1 chunk [64][65] / fW2 [128][65] / state [64][129]
    float* buf2 = sm + 8320;   // 4160 floats: obs chunk [64][65] / h [64][65]
    __shared__ int s_cnt[N_OPT];

    const int tid = threadIdx.x;
    const int r0  = blockIdx.x * TB;
    if (tid < N_OPT) s_cnt[tid] = 0;

    const int tr = tid & 15;   // row group  (4 rows)
    const int tc = tid >> 4;   // col group

    // ---------- phase 1: h = relu(obs @ fW1^T + fb1) ----------
    float acc[4][4];
#pragma unroll
    for (int i = 0; i < 4; i++)
#pragma unroll
        for (int j = 0; j < 4; j++) acc[i][j] = 0.f;

    for (int kc = 0; kc < OBS_DIM; kc += 64) {
#pragma unroll
        for (int i = 0; i < 16; i++) {
            int e = tid + i * 256;
            int row = e >> 6, k = e & 63;
            buf2[row * 65 + k] = obs[(r0 + row) * OBS_DIM + kc + k];
            buf1[row * 65 + k] = fW1[row * OBS_DIM + kc + k];   // row == hid index
        }
        __syncthreads();
#pragma unroll 8
        for (int kk = 0; kk < 64; kk++) {
            float a[4], b[4];
#pragma unroll
            for (int i = 0; i < 4; i++) a[i] = buf2[(4 * tr + i) * 65 + kk];
#pragma unroll
            for (int j = 0; j < 4; j++) b[j] = buf1[(4 * tc + j) * 65 + kk];
#pragma unroll
            for (int i = 0; i < 4; i++)
#pragma unroll
                for (int j = 0; j < 4; j++) acc[i][j] = fmaf(a[i], b[j], acc[i][j]);
        }
        __syncthreads();
    }
    // h -> buf2 [64][65]; load fW2 -> buf1 [128][65]
#pragma unroll
    for (int i = 0; i < 4; i++)
#pragma unroll
        for (int j = 0; j < 4; j++)
            buf2[(4 * tr + i) * 65 + 4 * tc + j] = fmaxf(acc[i][j] + fb1[4 * tc + j], 0.f);
#pragma unroll
    for (int i = 0; i < 32; i++) {
        int e = tid + i * 256;
        int f = e >> 6, k = e & 63;
        buf1[f * 65 + k] = fW2[f * HID + k];
    }
    __syncthreads();

    // ---------- phase 2: state = relu(h @ fW2^T + fb2) ----------
    float acc2[4][8];
#pragma unroll
    for (int i = 0; i < 4; i++)
#pragma unroll
        for (int j = 0; j < 8; j++) acc2[i][j] = 0.f;
#pragma unroll 8
    for (int kk = 0; kk < 64; kk++) {
        float a[4], b[8];
#pragma unroll
        for (int i = 0; i < 4; i++) a[i] = buf2[(4 * tr + i) * 65 + kk];
#pragma unroll
        for (int j = 0; j < 8; j++) b[j] = buf1[(8 * tc + j) * 65 + kk];
#pragma unroll
        for (int i = 0; i < 4; i++)
#pragma unroll
            for (int j = 0; j < 8; j++) acc2[i][j] = fmaf(a[i], b[j], acc2[i][j]);
    }
    __syncthreads();
    // state -> buf1 [64][129]
#pragma unroll
    for (int i = 0; i < 4; i++)
#pragma unroll
        for (int j = 0; j < 8; j++)
            buf1[(4 * tr + i) * 129 + 8 * tc + j] = fmaxf(acc2[i][j] + fb2[8 * tc + j], 0.f);
    __syncthreads();

    // copy state to global (coalesced)
#pragma unroll
    for (int i = 0; i < 32; i++) {
        int e = tid + i * 256;
        int row = e >> 7, f = e & 127;
        g_state[(r0 + row) * FEAT + f] = buf1[row * 129 + f];
    }

    // ---------- heads: warp per row ----------
    const int w = tid >> 5, lane = tid & 31;
#pragma unroll
    for (int q = 0; q < 8; q++) {
        int r = w * 8 + q;
        int gi = r0 + r;
        int o = opt[gi];
        float pv = 0.f, tv = 0.f;
#pragma unroll
        for (int j = 0; j < 4; j++) {
            float sv = buf1[r * 129 + 4 * lane + j];
            pv = fmaf(sv, pW[o * FEAT + 4 * lane + j], pv);
            tv = fmaf(sv, tW[o * FEAT + 4 * lane + j], tv);
        }
        pv = wred_sum(pv);
        tv = wred_sum(tv);
        if (lane == 0) {
            out_opt[gi]  = pv + pb[o];
            out_term[gi] = 1.f / (1.f + expf(-(tv + tb[o])));
        }
    }

    // ---------- histogram (block-aggregated) ----------
    if (tid < TB) atomicAdd(&s_cnt[opt[r0 + tid]], 1);
    __syncthreads();
    if (tid < N_OPT && s_cnt[tid]) atomicAdd(&g_counts[tid], s_cnt[tid]);
}

// =====================================================================
// Kernel 2: scan counts -> cursors (and reset counts for next replay)
// =====================================================================
__global__ void scan_kernel()
{
    if (threadIdx.x == 0) {
        int s = 0;
#pragma unroll
        for (int i = 0; i < N_OPT; i++) {
            int c = g_counts[i];
            g_cursor[i] = s;
            s += c;
            g_counts[i] = 0;
        }
    }
}

// =====================================================================
// Kernel 3: scatter rows into option-sorted permutation
// =====================================================================
__global__ void scatter_kernel(const int* __restrict__ opt)
{
    __shared__ int s_c[N_OPT];
    __shared__ int s_base[N_OPT];
    int t = threadIdx.x;
    if (t < N_OPT) s_c[t] = 0;
    __syncthreads();
    int i = blockIdx.x * blockDim.x + t;
    int o = opt[i];
    int loc = atomicAdd(&s_c[o], 1);
    __syncthreads();
    if (t < N_OPT) s_base[t] = atomicAdd(&g_cursor[t], s_c[t]);
    __syncthreads();
    g_perm[s_base[o] + loc] = i;
}

// =====================================================================
// Kernel 4: expert MLP on option-sorted tiles + log-softmax
// =====================================================================
__global__ void __launch_bounds__(256, 2) expert_kernel(
    const float* __restrict__ oW1, const float* __restrict__ ob1,
    const float* __restrict__ oW2, const float* __restrict__ ob2,
    const int* __restrict__ opt, const int* __restrict__ act,
    float* __restrict__ out_logp)
{
    extern __shared__ float sm[];
    float* s_st = sm;              // 64*129 = 8256
    float* s_w1 = sm + 8256;       // 64*129 = 8256
    float* s_eh = sm + 16512;      // 64*65  = 4160
    float* s_w2 = sm + 20672;      // 18*65  = 1170
    float* s_lg = sm + 21842;      // 64*19  = 1216
    __shared__ int s_idx[TB];
    __shared__ int s_opt[TB];

    const int tid = threadIdx.x;
    const int r0  = blockIdx.x * TB;

    if (tid < TB) {
        int gi = g_perm[r0 + tid];
        s_idx[tid] = gi;
        s_opt[tid] = opt[gi];
    }
    __syncthreads();
#pragma unroll
    for (int i = 0; i < 32; i++) {
        int e = tid + i * 256;
        int row = e >> 7, f = e & 127;
        s_st[row * 129 + f] = g_state[s_idx[row] * FEAT + f];
    }
    __syncthreads();

    const int tr = tid & 15, tc = tid >> 4;

    int j = 0;
    while (j < TB) {
        const int o = s_opt[j];
        int re = j + 1;
        while (re < TB && s_opt[re] == o) re++;

        // load oW1[o] [64][128] and oW2[o] [18][64]
#pragma unroll
        for (int i = 0; i < 32; i++) {
            int e = tid + i * 256;
            int h = e >> 7, f = e & 127;
            s_w1[h * 129 + f] = oW1[(o * HID + h) * FEAT + f];
        }
#pragma unroll
        for (int i = 0; i < 5; i++) {
            int e = tid + i * 256;
            if (e < ACT_N * HID) {
                int a = e >> 6, hh = e & 63;
                s_w2[a * 65 + hh] = oW2[o * ACT_N * HID + e];
            }
        }
        __syncthreads();

        // eh = relu(state @ W1^T + b1)  (dense over full tile; only run rows stored)
        float acc[4][4];
#pragma unroll
        for (int i = 0; i < 4; i++)
#pragma unroll
            for (int q = 0; q < 4; q++) acc[i][q] = 0.f;
#pragma unroll 8
        for (int f = 0; f < FEAT; f++) {
            float a[4], b[4];
#pragma unroll
            for (int i = 0; i < 4; i++) a[i] = s_st[(4 * tr + i) * 129 + f];
#pragma unroll
            for (int q = 0; q < 4; q++) b[q] = s_w1[(4 * tc + q) * 129 + f];
#pragma unroll
            for (int i = 0; i < 4; i++)
#pragma unroll
                for (int q = 0; q < 4; q++) acc[i][q] = fmaf(a[i], b[q], acc[i][q]);
        }
#pragma unroll
        for (int i = 0; i < 4; i++) {
            int rr = 4 * tr + i;
            if (rr >= j && rr < re) {
#pragma unroll
                for (int q = 0; q < 4; q++)
                    s_eh[rr * 65 + 4 * tc + q] =
                        fmaxf(acc[i][q] + ob1[o * HID + 4 * tc + q], 0.f);
            }
        }
        __syncthreads();

        // logits = eh @ W2^T + b2 for run rows
        int n = (re - j) * ACT_N;
        for (int t = tid; t < n; t += 256) {
            int rr = j + t / ACT_N;
            int a  = t % ACT_N;
            float s = 0.f;
#pragma unroll
            for (int h = 0; h < HID; h++)
                s = fmaf(s_eh[rr * 65 + h], s_w2[a * 65 + h], s);
            s_lg[rr * 19 + a] = s + ob2[o * ACT_N + a];
        }
        __syncthreads();
        j = re;
    }

    // log-softmax, warp per row
    const int w = tid >> 5, lane = tid & 31;
#pragma unroll
    for (int q = 0; q < 8; q++) {
        int r = w * 8 + q;
        float v = (lane < ACT_N) ? s_lg[r * 19 + lane] : -INFINITY;
        float m = wred_max(v);
        float ex = (lane < ACT_N) ? expf(v - m) : 0.f;
        float S = wred_sum(ex);
        int gi = s_idx[r];
        int a  = act[gi];
        float va = __shfl_sync(0xffffffffu, v, a);
        if (lane == 0) out_logp[gi] = va - m - logf(S);
    }
}

// =====================================================================
extern "C" void kernel_launch(void* const* d_in, const int* in_sizes, int n_in,
                              void* d_out, int out_size)
{
    const float* obs = (const float*)d_in[0];
    const int*   act = (const int*)  d_in[1];
    const int*   opt = (const int*)  d_in[2];
    const float* fW1 = (const float*)d_in[3];
    const float* fb1 = (const float*)d_in[4];
    const float* fW2 = (const float*)d_in[5];
    const float* fb2 = (const float*)d_in[6];
    const float* pW  = (const float*)d_in[7];
    const float* pb  = (const float*)d_in[8];
    const float* tW  = (const float*)d_in[9];
    const float* tb  = (const float*)d_in[10];
    const float* oW1 = (const float*)d_in[11];
    const float* ob1 = (const float*)d_in[12];
    const float* oW2 = (const float*)d_in[13];
    const float* ob2 = (const float*)d_in[14];

    float* out_logp = (float*)d_out;
    float* out_opt  = out_logp + B_TOT;
    float* out_term = out_logp + 2 * B_TOT;

    const int smem1 = (8320 + 4160) * (int)sizeof(float);   // 49,920 B
    const int smem4 = 23058 * (int)sizeof(float);           // 92,232 B
    cudaFuncSetAttribute(trunk_kernel,  cudaFuncAttributeMaxDynamicSharedMemorySize, smem1);
    cudaFuncSetAttribute(expert_kernel, cudaFuncAttributeMaxDynamicSharedMemorySize, smem4);

    trunk_kernel<<<B_TOT / TB, 256, smem1>>>(obs, opt, fW1, fb1, fW2, fb2,
                                             pW, pb, tW, tb, out_opt, out_term);
    scan_kernel<<<1, 32>>>();
    scatter_kernel<<<B_TOT / 256, 256>>>(opt);
    expert_kernel<<<B_TOT / TB, 256, smem4>>>(oW1, ob1, oW2, ob2, opt, act, out_logp);
}

// round 2
// speedup vs baseline: 1.1445x; 1.1445x over previous
#include <cuda_runtime.h>
#include <cuda_bf16.h>
#include <math.h>

#define B_TOT   32768
#define OBS_DIM 256
#define HID     64
#define FEAT    128
#define N_OPT   8
#define ACT_N   18
#define TB      64

typedef unsigned long long ull;

// ---------------- scratch (no allocation allowed) ----------------
__device__ float g_state[B_TOT * FEAT];
__device__ int   g_perm[B_TOT];
__device__ int   g_counts[N_OPT];
__device__ int   g_cursor[N_OPT];

// ---------------- packed f32x2 helpers ----------------
__device__ __forceinline__ ull ffma2(ull a, ull b, ull c) {
    ull d;
    asm("fma.rn.f32x2 %0, %1, %2, %3;" : "=l"(d) : "l"(a), "l"(b), "l"(c));
    return d;
}
__device__ __forceinline__ float f2sum(ull v) {
    float lo, hi;
    asm("mov.b64 {%0,%1}, %2;" : "=f"(lo), "=f"(hi) : "l"(v));
    return lo + hi;
}
__device__ __forceinline__ ull lds2(const float* p) {
    return *reinterpret_cast<const ull*>(p);
}

__device__ __forceinline__ float wred_sum(float v) {
#pragma unroll
    for (int o = 16; o; o >>= 1) v += __shfl_xor_sync(0xffffffffu, v, o);
    return v;
}
__device__ __forceinline__ float wred_max(float v) {
#pragma unroll
    for (int o = 16; o; o >>= 1) v = fmaxf(v, __shfl_xor_sync(0xffffffffu, v, o));
    return v;
}

// =====================================================================
// Kernel 1: trunk GEMMs + heads + option histogram
// smem: bufA 8448 floats (fW1 chunk / fW2 / state[64][130])
//       bufB 4224 floats (obs chunk / h[64][66])
// =====================================================================
__global__ void __launch_bounds__(256, 2) trunk_kernel(
    const float* __restrict__ obs, const int* __restrict__ opt,
    const float* __restrict__ fW1, const float* __restrict__ fb1,
    const float* __restrict__ fW2, const float* __restrict__ fb2,
    const float* __restrict__ pW,  const float* __restrict__ pb,
    const float* __restrict__ tW,  const float* __restrict__ tb,
    float* __restrict__ out_opt, float* __restrict__ out_term)
{
    extern __shared__ float sm[];
    float* bufA = sm;          // 8448
    float* bufB = sm + 8448;   // 4224
    __shared__ int s_cnt[N_OPT];

    const int tid = threadIdx.x;
    const int r0  = blockIdx.x * TB;
    if (tid < N_OPT) s_cnt[tid] = 0;

    const int tr = tid & 15;   // row group: rows tr + 16*i
    const int tc = tid >> 4;   // col group: cols tc + 16*j

    // ---------- phase 1: h = relu(obs @ fW1^T + fb1) ----------
    ull acc[4][4];
#pragma unroll
    for (int i = 0; i < 4; i++)
#pragma unroll
        for (int j = 0; j < 4; j++) acc[i][j] = 0ull;

    for (int kc = 0; kc < OBS_DIM; kc += 64) {
#pragma unroll
        for (int it = 0; it < 8; it++) {
            int e = tid + it * 256;              // 2048 float2 slots
            int row = e >> 5, kk = (e & 31) << 1;
            *(float2*)(bufB + row * 66 + kk) =
                *(const float2*)(obs + (r0 + row) * OBS_DIM + kc + kk);
            *(float2*)(bufA + row * 66 + kk) =
                *(const float2*)(fW1 + row * OBS_DIM + kc + kk);
        }
        __syncthreads();
#pragma unroll 8
        for (int k = 0; k < 64; k += 2) {
            ull a[4], b[4];
#pragma unroll
            for (int i = 0; i < 4; i++) a[i] = lds2(bufB + (tr + 16 * i) * 66 + k);
#pragma unroll
            for (int j = 0; j < 4; j++) b[j] = lds2(bufA + (tc + 16 * j) * 66 + k);
#pragma unroll
            for (int i = 0; i < 4; i++)
#pragma unroll
                for (int j = 0; j < 4; j++) acc[i][j] = ffma2(a[i], b[j], acc[i][j]);
        }
        __syncthreads();
    }
    // h -> bufB [64][66]
#pragma unroll
    for (int i = 0; i < 4; i++)
#pragma unroll
        for (int j = 0; j < 4; j++)
            bufB[(tr + 16 * i) * 66 + tc + 16 * j] =
                fmaxf(f2sum(acc[i][j]) + fb1[tc + 16 * j], 0.f);
    // fW2 -> bufA [128][66]
#pragma unroll
    for (int it = 0; it < 16; it++) {
        int e = tid + it * 256;                  // 4096 float2 slots
        int f = e >> 5, kk = (e & 31) << 1;
        *(float2*)(bufA + f * 66 + kk) = *(const float2*)(fW2 + f * HID + kk);
    }
    __syncthreads();

    // ---------- phase 2: state = relu(h @ fW2^T + fb2) ----------
    ull acc2[4][8];
#pragma unroll
    for (int i = 0; i < 4; i++)
#pragma unroll
        for (int j = 0; j < 8; j++) acc2[i][j] = 0ull;
#pragma unroll 8
    for (int k = 0; k < 64; k += 2) {
        ull a[4];
#pragma unroll
        for (int i = 0; i < 4; i++) a[i] = lds2(bufB + (tr + 16 * i) * 66 + k);
#pragma unroll
        for (int j = 0; j < 8; j++) {
            ull b = lds2(bufA + (tc + 16 * j) * 66 + k);
#pragma unroll
            for (int i = 0; i < 4; i++) acc2[i][j] = ffma2(a[i], b, acc2[i][j]);
        }
    }
    __syncthreads();
    // state -> bufA [64][130]
#pragma unroll
    for (int i = 0; i < 4; i++)
#pragma unroll
        for (int j = 0; j < 8; j++)
            bufA[(tr + 16 * i) * 130 + tc + 16 * j] =
                fmaxf(f2sum(acc2[i][j]) + fb2[tc + 16 * j], 0.f);
    __syncthreads();

    // copy state to global (coalesced, float2)
#pragma unroll
    for (int it = 0; it < 16; it++) {
        int e = tid + it * 256;                  // 4096 float2 slots
        int row = e >> 6, f2i = (e & 63) << 1;
        *(float2*)(g_state + (r0 + row) * FEAT + f2i) =
            *(const float2*)(bufA + row * 130 + f2i);
    }

    // ---------- heads: warp per row ----------
    const int w = tid >> 5, lane = tid & 31;
#pragma unroll
    for (int q = 0; q < 8; q++) {
        int r = w * 8 + q;
        int gi = r0 + r;
        int o = opt[gi];
        ull pv = 0ull, tv = 0ull;
#pragma unroll
        for (int j = 0; j < 2; j++) {
            ull sv = lds2(bufA + r * 130 + 4 * lane + 2 * j);
            pv = ffma2(sv, *(const ull*)(pW + o * FEAT + 4 * lane + 2 * j), pv);
            tv = ffma2(sv, *(const ull*)(tW + o * FEAT + 4 * lane + 2 * j), tv);
        }
        float pvs = wred_sum(f2sum(pv));
        float tvs = wred_sum(f2sum(tv));
        if (lane == 0) {
            out_opt[gi]  = pvs + pb[o];
            out_term[gi] = 1.f / (1.f + expf(-(tvs + tb[o])));
        }
    }

    // ---------- histogram ----------
    if (tid < TB) atomicAdd(&s_cnt[opt[r0 + tid]], 1);
    __syncthreads();
    if (tid < N_OPT && s_cnt[tid]) atomicAdd(&g_counts[tid], s_cnt[tid]);
}

// =====================================================================
__global__ void scan_kernel()
{
    if (threadIdx.x == 0) {
        int s = 0;
#pragma unroll
        for (int i = 0; i < N_OPT; i++) {
            int c = g_counts[i];
            g_cursor[i] = s;
            s += c;
            g_counts[i] = 0;
        }
    }
}

__global__ void scatter_kernel(const int* __restrict__ opt)
{
    __shared__ int s_c[N_OPT];
    __shared__ int s_base[N_OPT];
    int t = threadIdx.x;
    if (t < N_OPT) s_c[t] = 0;
    __syncthreads();
    int i = blockIdx.x * blockDim.x + t;
    int o = opt[i];
    int loc = atomicAdd(&s_c[o], 1);
    __syncthreads();
    if (t < N_OPT) s_base[t] = atomicAdd(&g_cursor[t], s_c[t]);
    __syncthreads();
    g_perm[s_base[o] + loc] = i;
}

// =====================================================================
// Kernel 4: expert MLP on option-sorted tiles + log-softmax
// =====================================================================
__global__ void __launch_bounds__(256, 2) expert_kernel(
    const float* __restrict__ oW1, const float* __restrict__ ob1,
    const float* __restrict__ oW2, const float* __restrict__ ob2,
    const int* __restrict__ opt, const int* __restrict__ act,
    float* __restrict__ out_logp)
{
    extern __shared__ float sm[];
    float* s_st = sm;              // 64*130 = 8320
    float* s_w1 = sm + 8320;       // 64*130 = 8320
    float* s_eh = sm + 16640;      // 64*66  = 4224
    float* s_w2 = sm + 20864;      // 18*66  = 1188
    float* s_lg = sm + 22052;      // 64*19  = 1216
    __shared__ int s_idx[TB];
    __shared__ int s_opt[TB];

    const int tid = threadIdx.x;
    const int r0  = blockIdx.x * TB;

    if (tid < TB) {
        int gi = g_perm[r0 + tid];
        s_idx[tid] = gi;
        s_opt[tid] = opt[gi];
    }
    __syncthreads();
#pragma unroll
    for (int it = 0; it < 16; it++) {
        int e = tid + it * 256;                  // 4096 float2 slots
        int row = e >> 6, f2i = (e & 63) << 1;
        *(float2*)(s_st + row * 130 + f2i) =
            *(const float2*)(g_state + s_idx[row] * FEAT + f2i);
    }
    __syncthreads();

    const int tr = tid & 15, tc = tid >> 4;

    int j = 0;
    while (j < TB) {
        const int o = s_opt[j];
        int re = j + 1;
        while (re < TB && s_opt[re] == o) re++;

        // load oW1[o] [64][128] and oW2[o] [18][64]
#pragma unroll
        for (int it = 0; it < 16; it++) {
            int e = tid + it * 256;
            int h = e >> 6, f2i = (e & 63) << 1;
            *(float2*)(s_w1 + h * 130 + f2i) =
                *(const float2*)(oW1 + (o * HID + h) * FEAT + f2i);
        }
#pragma unroll
        for (int it = 0; it < 3; it++) {
            int e = tid + it * 256;              // 576 float2 slots
            if (e < ACT_N * 32) {
                int a = e >> 5, h2 = (e & 31) << 1;
                *(float2*)(s_w2 + a * 66 + h2) =
                    *(const float2*)(oW2 + o * ACT_N * HID + a * HID + h2);
            }
        }
        __syncthreads();

        // eh = relu(state @ W1^T + b1)
        ull acc[4][4];
#pragma unroll
        for (int i = 0; i < 4; i++)
#pragma unroll
            for (int q = 0; q < 4; q++) acc[i][q] = 0ull;
#pragma unroll 8
        for (int k = 0; k < FEAT; k += 2) {
            ull a[4], b[4];
#pragma unroll
            for (int i = 0; i < 4; i++) a[i] = lds2(s_st + (tr + 16 * i) * 130 + k);
#pragma unroll
            for (int q = 0; q < 4; q++) b[q] = lds2(s_w1 + (tc + 16 * q) * 130 + k);
#pragma unroll
            for (int i = 0; i < 4; i++)
#pragma unroll
                for (int q = 0; q < 4; q++) acc[i][q] = ffma2(a[i], b[q], acc[i][q]);
        }
#pragma unroll
        for (int i = 0; i < 4; i++) {
            int rr = tr + 16 * i;
            if (rr >= j && rr < re) {
#pragma unroll
                for (int q = 0; q < 4; q++) {
                    int cc = tc + 16 * q;
                    s_eh[rr * 66 + cc] =
                        fmaxf(f2sum(acc[i][q]) + ob1[o * HID + cc], 0.f);
                }
            }
        }
        __syncthreads();

        // logits = eh @ W2^T + b2 for run rows
        int n = (re - j) * ACT_N;
        for (int t = tid; t < n; t += 256) {
            int rr = j + t / ACT_N;
            int a  = t % ACT_N;
            ull s = 0ull;
#pragma unroll
            for (int h = 0; h < HID; h += 2)
                s = ffma2(lds2(s_eh + rr * 66 + h), lds2(s_w2 + a * 66 + h), s);
            s_lg[rr * 19 + a] = f2sum(s) + ob2[o * ACT_N + a];
        }
        __syncthreads();
        j = re;
    }

    // log-softmax, warp per row
    const int w = tid >> 5, lane = tid & 31;
#pragma unroll
    for (int q = 0; q < 8; q++) {
        int r = w * 8 + q;
        float v = (lane < ACT_N) ? s_lg[r * 19 + lane] : -INFINITY;
        float m = wred_max(v);
        float ex = (lane < ACT_N) ? expf(v - m) : 0.f;
        float S = wred_sum(ex);
        int gi = s_idx[r];
        int a  = act[gi];
        float va = __shfl_sync(0xffffffffu, v, a);
        if (lane == 0) out_logp[gi] = va - m - logf(S);
    }
}

// =====================================================================
extern "C" void kernel_launch(void* const* d_in, const int* in_sizes, int n_in,
                              void* d_out, int out_size)
{
    const float* obs = (const float*)d_in[0];
    const int*   act = (const int*)  d_in[1];
    const int*   opt = (const int*)  d_in[2];
    const float* fW1 = (const float*)d_in[3];
    const float* fb1 = (const float*)d_in[4];
    const float* fW2 = (const float*)d_in[5];
    const float* fb2 = (const float*)d_in[6];
    const float* pW  = (const float*)d_in[7];
    const float* pb  = (const float*)d_in[8];
    const float* tW  = (const float*)d_in[9];
    const float* tb  = (const float*)d_in[10];
    const float* oW1 = (const float*)d_in[11];
    const float* ob1 = (const float*)d_in[12];
    const float* oW2 = (const float*)d_in[13];
    const float* ob2 = (const float*)d_in[14];

    float* out_logp = (float*)d_out;
    float* out_opt  = out_logp + B_TOT;
    float* out_term = out_logp + 2 * B_TOT;

    const int smem1 = (8448 + 4224) * (int)sizeof(float);   // 50,688 B
    const int smem4 = 23268 * (int)sizeof(float);           // 93,072 B
    cudaFuncSetAttribute(trunk_kernel,  cudaFuncAttributeMaxDynamicSharedMemorySize, smem1);
    cudaFuncSetAttribute(expert_kernel, cudaFuncAttributeMaxDynamicSharedMemorySize, smem4);

    trunk_kernel<<<B_TOT / TB, 256, smem1>>>(obs, opt, fW1, fb1, fW2, fb2,
                                             pW, pb, tW, tb, out_opt, out_term);
    scan_kernel<<<1, 32>>>();
    scatter_kernel<<<B_TOT / 256, 256>>>(opt);
    expert_kernel<<<B_TOT / TB, 256, smem4>>>(oW1, ob1, oW2, ob2, opt, act, out_logp);
}